// round 11
// baseline (speedup 1.0000x reference)
#include <cuda_runtime.h>
#include <cstdint>

// out[r, c] = x[r, c] * diag[c], x: 16384 x 2048 f32.
// Final design-matrix cell: v8 (256-bit) accesses x MLP_p1=4.
// Each thread: 4 chunks of 8 floats, same column, 4 consecutive rows
// (1 row = 2048 floats apart). 4 front-batched independent v8 loads =
// 4KB/warp in flight at issue; one diag load serves all 4 rows.
// .cs evict-first on single-touch streams. Exact grid 4096 x 256.

#define ROW_F 2048u

__global__ __launch_bounds__(256) void diag_scale_kernel(
    const float* __restrict__ x,
    const float* __restrict__ d,
    float* __restrict__ out)
{
    unsigned int t = blockIdx.x * 256u + threadIdx.x;     // 0 .. 1,048,575
    unsigned int col8 = (t & 255u) * 8u;                  // float column of chunk
    unsigned int rowquad = t >> 8;                        // group of 4 rows
    size_t base = (size_t)rowquad * (4u * ROW_F) + col8;

    const float* xp = x + base;
    float*       op = out + base;
    const float* dp = d + col8;

    float a0,a1,a2,a3,a4,a5,a6,a7;
    float b0,b1,b2,b3,b4,b5,b6,b7;
    float c0,c1,c2,c3,c4,c5,c6,c7;
    float e0,e1,e2,e3,e4,e5,e6,e7;
    asm volatile(
        "ld.global.cs.v8.f32 {%0,%1,%2,%3,%4,%5,%6,%7}, [%8];"
        : "=f"(a0),"=f"(a1),"=f"(a2),"=f"(a3),
          "=f"(a4),"=f"(a5),"=f"(a6),"=f"(a7)
        : "l"(xp));
    asm volatile(
        "ld.global.cs.v8.f32 {%0,%1,%2,%3,%4,%5,%6,%7}, [%8];"
        : "=f"(b0),"=f"(b1),"=f"(b2),"=f"(b3),
          "=f"(b4),"=f"(b5),"=f"(b6),"=f"(b7)
        : "l"(xp + ROW_F));
    asm volatile(
        "ld.global.cs.v8.f32 {%0,%1,%2,%3,%4,%5,%6,%7}, [%8];"
        : "=f"(c0),"=f"(c1),"=f"(c2),"=f"(c3),
          "=f"(c4),"=f"(c5),"=f"(c6),"=f"(c7)
        : "l"(xp + 2u * ROW_F));
    asm volatile(
        "ld.global.cs.v8.f32 {%0,%1,%2,%3,%4,%5,%6,%7}, [%8];"
        : "=f"(e0),"=f"(e1),"=f"(e2),"=f"(e3),
          "=f"(e4),"=f"(e5),"=f"(e6),"=f"(e7)
        : "l"(xp + 3u * ROW_F));

    float s0,s1,s2,s3,s4,s5,s6,s7;
    asm volatile(
        "ld.global.nc.v8.f32 {%0,%1,%2,%3,%4,%5,%6,%7}, [%8];"
        : "=f"(s0),"=f"(s1),"=f"(s2),"=f"(s3),
          "=f"(s4),"=f"(s5),"=f"(s6),"=f"(s7)
        : "l"(dp));

    a0*=s0; a1*=s1; a2*=s2; a3*=s3; a4*=s4; a5*=s5; a6*=s6; a7*=s7;
    b0*=s0; b1*=s1; b2*=s2; b3*=s3; b4*=s4; b5*=s5; b6*=s6; b7*=s7;
    c0*=s0; c1*=s1; c2*=s2; c3*=s3; c4*=s4; c5*=s5; c6*=s6; c7*=s7;
    e0*=s0; e1*=s1; e2*=s2; e3*=s3; e4*=s4; e5*=s5; e6*=s6; e7*=s7;

    asm volatile(
        "st.global.cs.v8.f32 [%0], {%1,%2,%3,%4,%5,%6,%7,%8};"
        :: "l"(op),
           "f"(a0),"f"(a1),"f"(a2),"f"(a3),
           "f"(a4),"f"(a5),"f"(a6),"f"(a7)
        : "memory");
    asm volatile(
        "st.global.cs.v8.f32 [%0], {%1,%2,%3,%4,%5,%6,%7,%8};"
        :: "l"(op + ROW_F),
           "f"(b0),"f"(b1),"f"(b2),"f"(b3),
           "f"(b4),"f"(b5),"f"(b6),"f"(b7)
        : "memory");
    asm volatile(
        "st.global.cs.v8.f32 [%0], {%1,%2,%3,%4,%5,%6,%7,%8};"
        :: "l"(op + 2u * ROW_F),
           "f"(c0),"f"(c1),"f"(c2),"f"(c3),
           "f"(c4),"f"(c5),"f"(c6),"f"(c7)
        : "memory");
    asm volatile(
        "st.global.cs.v8.f32 [%0], {%1,%2,%3,%4,%5,%6,%7,%8};"
        :: "l"(op + 3u * ROW_F),
           "f"(e0),"f"(e1),"f"(e2),"f"(e3),
           "f"(e4),"f"(e5),"f"(e6),"f"(e7)
        : "memory");
}

extern "C" void kernel_launch(void* const* d_in, const int* in_sizes, int n_in,
                              void* d_out, int out_size) {
    const float* x = (const float*)d_in[0];
    const float* d = (const float*)d_in[1];
    float* out = (float*)d_out;

    // 16384*2048 floats / 32 per thread = 1,048,576 threads -> 4096 blocks
    const int threads = 256;
    const int blocks = (16384 * 2048 / 32) / threads;  // 4096, exact

    diag_scale_kernel<<<blocks, threads>>>(x, d, out);
}